// round 8
// baseline (speedup 1.0000x reference)
#include <cuda_runtime.h>
#include <cstdint>

#define BDIM 288
#define DISP 4
#define ND 9
#define CH 128
#define HH 96
#define WW 160
#define NB 8
#define TY 8
#define TX 32
#define CCH 4
#define NBUF 3
#define NSTAGE (CH / CCH)        // 32
#define FRS 36
#define FCS (TY * FRS)           // 288 floats / channel
#define SRS 44
#define SROWS (TY + 2 * DISP)    // 16
#define SCS (SROWS * SRS)        // 704 floats / channel
#define CHB (HH * WW * 4)        // bytes per channel plane

typedef unsigned long long u64;
typedef unsigned int u32;

struct F2 { float lo, hi; };
struct EW { ulonglong2 e01, e23, e45, e67; };

static __device__ __forceinline__ u64 pk(float lo, float hi) {
    u64 r; asm("mov.b64 %0, {%1, %2};" : "=l"(r) : "f"(lo), "f"(hi)); return r;
}
static __device__ __forceinline__ F2 unp(u64 v) {
    F2 r; asm("mov.b64 {%0, %1}, %2;" : "=f"(r.lo), "=f"(r.hi) : "l"(v)); return r;
}
static __device__ __forceinline__ void fma2(u64 &d, u64 a, u64 b) {
    asm("fma.rn.f32x2 %0, %1, %2, %0;" : "+l"(d) : "l"(a), "l"(b));
}
static __device__ __forceinline__ void cpa16(u32 saddr, const void* gptr, int srcsz) {
    asm volatile("cp.async.cg.shared.global [%0], [%1], 16, %2;"
                 :: "r"(saddr), "l"(gptr), "r"(srcsz));
}
static __device__ __forceinline__ void cpa_commit() {
    asm volatile("cp.async.commit_group;");
}
template <int N> static __device__ __forceinline__ void cpa_wait() {
    asm volatile("cp.async.wait_group %0;" :: "n"(N));
}

__global__ __launch_bounds__(BDIM, 2)
void corr_kernel(const float* __restrict__ first,
                 const float* __restrict__ second,
                 float* __restrict__ out) {
    __shared__ __align__(16) float sF[NBUF][CCH * FCS];   // 13824 B
    __shared__ __align__(16) float sS[NBUF][CCH * SCS];   // 33792 B

    const int tid = threadIdx.x;
    const int b   = blockIdx.z;
    const int y0  = blockIdx.y * TY;
    const int x0  = blockIdx.x * TX;

    const int d    = tid >> 5;
    const int lane = tid & 31;
    const int ty   = lane >> 2;
    const int xg   = lane & 3;

    const u32 sF0 = (u32)__cvta_generic_to_shared(&sF[0][0]);
    const u32 sS0 = (u32)__cvta_generic_to_shared(&sS[0][0]);

    // ---- persistent staging assignments (32-bit byte offsets) ----
    u32 g2off = 0, soff2 = 0; int ok2 = 0;
    u32 g1off0 = 0, g1off1 = 0, soff1_0 = 0, soff1_1 = 0;

    if (tid < 160) {
        const int r2 = tid / 10;
        const int q2 = tid - r2 * 10;
        const int gy = y0 - DISP + r2;
        const int gx = x0 - DISP + 4 * q2;
        ok2 = (((unsigned)gy < HH) && ((unsigned)gx <= (WW - 4))) ? 16 : 0;
        const int cgy = ok2 ? gy : 0;
        const int cgx = ok2 ? gx : 0;
        g2off = (u32)(((b * CH * HH + cgy) * WW + cgx) * 4);
        soff2 = (u32)((r2 * SRS + 4 * q2) * 4);
    } else {
        const int i = tid - 160;
        #pragma unroll
        for (int k = 0; k < 2; k++) {
            const int qid = 2 * i + k;
            const int ca  = qid >> 6;
            const int p   = qid & 63;
            const int ra  = p >> 3;
            const int xqa = p & 7;
            const u32 go = (u32)((((b * CH + ca) * HH + y0 + ra) * WW + x0 + 4 * xqa) * 4);
            const u32 so = (u32)((ca * FCS + ra * FRS + 4 * xqa) * 4);
            if (k == 0) { g1off0 = go; soff1_0 = so; } else { g1off1 = go; soff1_1 = so; }
        }
    }

    const char* firstB  = (const char*)first;
    const char* secondB = (const char*)second;

    u64 acc[36];
    #pragma unroll
    for (int i = 0; i < 36; i++) acc[i] = 0ull;

    auto stage = [&](int s, int bi) {
        const u32 coff = (u32)(s * CCH) * (u32)CHB;
        if (tid < 160) {
            const u32 sSb = sS0 + (u32)(bi * CCH * SCS * 4) + soff2;
            #pragma unroll
            for (int c = 0; c < CCH; c++)
                cpa16(sSb + (u32)(c * SCS * 4), secondB + g2off + coff + c * CHB, ok2);
        } else {
            const u32 sFb = sF0 + (u32)(bi * CCH * FCS * 4);
            cpa16(sFb + soff1_0, firstB + g1off0 + coff, 16);
            cpa16(sFb + soff1_1, firstB + g1off1 + coff, 16);
        }
    };

    auto compute = [&](int br) {   // br compile-time
        const float* fptr = &sF[br][ty * FRS + 8 * xg];
        const float* sptr = &sS[br][(ty + d) * SRS + 8 * xg];

        EW cur;
        cur.e01 = *reinterpret_cast<const ulonglong2*>(sptr);
        cur.e23 = *reinterpret_cast<const ulonglong2*>(sptr + 4);
        cur.e45 = *reinterpret_cast<const ulonglong2*>(sptr + 8);
        cur.e67 = *reinterpret_cast<const ulonglong2*>(sptr + 12);

        #pragma unroll
        for (int cc = 0; cc < CCH; cc++) {
            EW nxt;
            if (cc + 1 < CCH) {
                const float* sp = sptr + (cc + 1) * SCS;
                nxt.e01 = *reinterpret_cast<const ulonglong2*>(sp);
                nxt.e23 = *reinterpret_cast<const ulonglong2*>(sp + 4);
                nxt.e45 = *reinterpret_cast<const ulonglong2*>(sp + 8);
                nxt.e67 = *reinterpret_cast<const ulonglong2*>(sp + 12);
            }
            const ulonglong2 F01 = *reinterpret_cast<const ulonglong2*>(fptr + cc * FCS);
            const ulonglong2 F23 = *reinterpret_cast<const ulonglong2*>(fptr + cc * FCS + 4);

            const F2 a0 = unp(cur.e01.x), a1 = unp(cur.e01.y);
            const F2 a2 = unp(cur.e23.x), a3 = unp(cur.e23.y);
            const F2 a4 = unp(cur.e45.x), a5 = unp(cur.e45.y);
            const F2 a6 = unp(cur.e67.x), a7 = unp(cur.e67.y);

            u64 P[15];
            P[0]  = cur.e01.x;        P[2]  = cur.e01.y;
            P[4]  = cur.e23.x;        P[6]  = cur.e23.y;
            P[8]  = cur.e45.x;        P[10] = cur.e45.y;
            P[12] = cur.e67.x;        P[14] = cur.e67.y;
            P[1]  = pk(a0.hi, a1.lo); P[3]  = pk(a1.hi, a2.lo);
            P[5]  = pk(a2.hi, a3.lo); P[7]  = pk(a3.hi, a4.lo);
            P[9]  = pk(a4.hi, a5.lo); P[11] = pk(a5.hi, a6.lo);
            P[13] = pk(a6.hi, a7.lo);

            #pragma unroll
            for (int j = 0; j < ND; j++) {
                fma2(acc[j],      F01.x, P[j]);
                fma2(acc[9 + j],  F01.y, P[2 + j]);
                fma2(acc[18 + j], F23.x, P[4 + j]);
                fma2(acc[27 + j], F23.y, P[6 + j]);
            }
            if (cc + 1 < CCH) cur = nxt;
        }
    };

    // mode 0: wait<1>, sync, stage(s+2); mode 1: wait<1>, sync; mode 2: wait<0>, sync
    auto iter = [&](int s, int br, int bw, int mode) {
        if (mode == 0) {
            cpa_wait<1>();
            __syncthreads();
            stage(s + 2, bw);
            cpa_commit();
        } else if (mode == 1) {
            cpa_wait<1>();
            __syncthreads();
        } else {
            cpa_wait<0>();
            __syncthreads();
        }
        compute(br);
        // NOTE: no trailing sync — the post-wait sync of the next iteration
        // already orders this compute before any overwrite of its buffer.
    };

    stage(0, 0); cpa_commit();
    stage(1, 1); cpa_commit();

    #pragma unroll 1
    for (int t = 0; t < 10; t++) {
        const int s = 3 * t;
        iter(s + 0, 0, 2, 0);
        iter(s + 1, 1, 0, 0);
        iter(s + 2, 2, 1, 0);
    }
    iter(30, 0, 2, 1);
    iter(31, 1, 0, 2);

    // ---- epilogue: chan = dy*9 + dx (dx fastest) ----
    const float inv_c = 1.0f / (float)CH;
    const int gy = y0 + ty;
    const int gx = x0 + 8 * xg;
    char* outB = (char*)out;
    u32 obase = (u32)((((b * 81 + d * ND) * HH + gy) * WW + gx) * 4);
    #pragma unroll
    for (int j = 0; j < ND; j++) {
        float* o = (float*)(outB + obase);
        obase += (u32)(HH * WW * 4);
        const F2 r0 = unp(acc[j]);
        const F2 r1 = unp(acc[9 + j]);
        const F2 r2 = unp(acc[18 + j]);
        const F2 r3 = unp(acc[27 + j]);
        float4 v0 = make_float4(r0.lo * inv_c, r0.hi * inv_c, r1.lo * inv_c, r1.hi * inv_c);
        float4 v1 = make_float4(r2.lo * inv_c, r2.hi * inv_c, r3.lo * inv_c, r3.hi * inv_c);
        *reinterpret_cast<float4*>(o)     = v0;
        *reinterpret_cast<float4*>(o + 4) = v1;
    }
}

extern "C" void kernel_launch(void* const* d_in, const int* in_sizes, int n_in,
                              void* d_out, int out_size) {
    const float* first  = (const float*)d_in[0];
    const float* second = (const float*)d_in[1];
    float* out = (float*)d_out;
    (void)in_sizes; (void)n_in; (void)out_size;

    dim3 grid(WW / TX, HH / TY, NB);   // (5, 12, 8)
    corr_kernel<<<grid, BDIM>>>(first, second, out);
}

// round 9
// speedup vs baseline: 1.5134x; 1.5134x over previous
#include <cuda_runtime.h>
#include <cuda.h>
#include <cstdint>

#define BDIM 288
#define DISP 4
#define ND 9
#define CH 128
#define HH 96
#define WW 160
#define NB 8
#define TY 8
#define TX 32
#define CCH 4
#define NBUF 3
#define NSTAGE (CH / CCH)        // 32
// TMA-packed layouts
#define FRS 32                   // first tile row stride (floats)
#define FCS (TY * FRS)           // 256 floats / channel
#define SRS 40                   // second tile row stride (floats)
#define SROWS (TY + 2 * DISP)    // 16
#define SCS (SROWS * SRS)        // 640 floats / channel
#define SBYTES (CCH * SCS * 4)   // 10240
#define FBYTES (CCH * FCS * 4)   // 4096
#define STAGE_BYTES (SBYTES + FBYTES)  // 14336

typedef unsigned long long u64;
typedef unsigned int u32;

struct F2 { float lo, hi; };

static __device__ __forceinline__ u64 pk(float lo, float hi) {
    u64 r; asm("mov.b64 %0, {%1, %2};" : "=l"(r) : "f"(lo), "f"(hi)); return r;
}
static __device__ __forceinline__ F2 unp(u64 v) {
    F2 r; asm("mov.b64 {%0, %1}, %2;" : "=f"(r.lo), "=f"(r.hi) : "l"(v)); return r;
}
static __device__ __forceinline__ void fma2(u64 &d, u64 a, u64 b) {
    asm("fma.rn.f32x2 %0, %1, %2, %0;" : "+l"(d) : "l"(a), "l"(b));
}

#define MBAR_INIT(addr, cnt) \
    asm volatile("mbarrier.init.shared.b64 [%0], %1;" :: "r"(addr), "r"(cnt) : "memory")
#define MBAR_EXPECT_TX(addr, bytes) \
    asm volatile("mbarrier.arrive.expect_tx.shared.b64 _, [%0], %1;" :: "r"(addr), "r"(bytes) : "memory")
#define TMA_LD3D(smem, tmap, cx, cy, cz, mbar) \
    asm volatile("cp.async.bulk.tensor.3d.shared::cta.global.tile.mbarrier::complete_tx::bytes " \
                 "[%0], [%1, {%2, %3, %4}], [%5];" \
                 :: "r"(smem), "l"(tmap), "r"(cx), "r"(cy), "r"(cz), "r"(mbar) : "memory")

static __device__ __forceinline__ void mbar_wait(u32 addr, u32 phase) {
    asm volatile(
        "{\n\t"
        ".reg .pred P1;\n\t"
        "WAIT_LOOP_%=:\n\t"
        "mbarrier.try_wait.parity.acquire.cta.shared::cta.b64 P1, [%0], %1, 0x989680;\n\t"
        "@P1 bra.uni WAIT_DONE_%=;\n\t"
        "bra.uni WAIT_LOOP_%=;\n\t"
        "WAIT_DONE_%=:\n\t"
        "}"
        :: "r"(addr), "r"(phase) : "memory");
}

__global__ __launch_bounds__(BDIM, 2)
void corr_kernel(const float* __restrict__ first,
                 const float* __restrict__ second,
                 float* __restrict__ out,
                 const __grid_constant__ CUtensorMap tmF,
                 const __grid_constant__ CUtensorMap tmS) {
    __shared__ __align__(1024) float sS[NBUF][CCH * SCS];   // 30720 B
    __shared__ __align__(1024) float sF[NBUF][CCH * FCS];   // 12288 B
    __shared__ __align__(8) u64 mbars[NBUF];

    const int tid = threadIdx.x;
    const int b   = blockIdx.z;
    const int y0  = blockIdx.y * TY;
    const int x0  = blockIdx.x * TX;

    const int d    = tid >> 5;      // dy 0..8
    const int lane = tid & 31;
    const int ty   = lane >> 2;     // 0..7
    const int xg   = lane & 3;      // 0..3

    const u32 mb0 = (u32)__cvta_generic_to_shared(&mbars[0]);
    const u32 sS0 = (u32)__cvta_generic_to_shared(&sS[0][0]);
    const u32 sF0 = (u32)__cvta_generic_to_shared(&sF[0][0]);

    if (tid == 0) {
        MBAR_INIT(mb0 + 0,  1);
        MBAR_INIT(mb0 + 8,  1);
        MBAR_INIT(mb0 + 16, 1);
    }
    __syncthreads();

    const int zbase = b * CH;

    auto issue = [&](int s, int bi) {
        if (tid == 0) {
            const u32 mb = mb0 + bi * 8;
            MBAR_EXPECT_TX(mb, STAGE_BYTES);
            TMA_LD3D(sS0 + bi * SBYTES, &tmS, x0 - DISP, y0 - DISP, zbase + s * CCH, mb);
            TMA_LD3D(sF0 + bi * FBYTES, &tmF, x0,        y0,        zbase + s * CCH, mb);
        }
    };

    u64 acc[36];
    #pragma unroll
    for (int i = 0; i < 36; i++) acc[i] = 0ull;

    auto compute = [&](int bi) {   // bi compile-time
        const float* fptr = &sF[bi][ty * FRS + 8 * xg];
        const float* sptr = &sS[bi][(ty + d) * SRS + 8 * xg];
        #pragma unroll
        for (int cc = 0; cc < CCH; cc++) {
            const ulonglong2 F01 = *reinterpret_cast<const ulonglong2*>(fptr + cc * FCS);
            const ulonglong2 F23 = *reinterpret_cast<const ulonglong2*>(fptr + cc * FCS + 4);
            const ulonglong2 E01 = *reinterpret_cast<const ulonglong2*>(sptr + cc * SCS);
            const ulonglong2 E23 = *reinterpret_cast<const ulonglong2*>(sptr + cc * SCS + 4);
            const ulonglong2 E45 = *reinterpret_cast<const ulonglong2*>(sptr + cc * SCS + 8);
            const ulonglong2 E67 = *reinterpret_cast<const ulonglong2*>(sptr + cc * SCS + 12);

            const F2 a0 = unp(E01.x), a1 = unp(E01.y);
            const F2 a2 = unp(E23.x), a3 = unp(E23.y);
            const F2 a4 = unp(E45.x), a5 = unp(E45.y);
            const F2 a6 = unp(E67.x), a7 = unp(E67.y);

            u64 P[15];
            P[0]  = E01.x;            P[2]  = E01.y;
            P[4]  = E23.x;            P[6]  = E23.y;
            P[8]  = E45.x;            P[10] = E45.y;
            P[12] = E67.x;            P[14] = E67.y;
            P[1]  = pk(a0.hi, a1.lo); P[3]  = pk(a1.hi, a2.lo);
            P[5]  = pk(a2.hi, a3.lo); P[7]  = pk(a3.hi, a4.lo);
            P[9]  = pk(a4.hi, a5.lo); P[11] = pk(a5.hi, a6.lo);
            P[13] = pk(a6.hi, a7.lo);

            #pragma unroll
            for (int j = 0; j < ND; j++) {
                fma2(acc[j],      F01.x, P[j]);
                fma2(acc[9 + j],  F01.y, P[2 + j]);
                fma2(acc[18 + j], F23.x, P[4 + j]);
                fma2(acc[27 + j], F23.y, P[6 + j]);
            }
        }
    };

    auto body = [&](int s, int bi, u32 ph) {
        mbar_wait(mb0 + bi * 8, ph);
        compute(bi);
        __syncthreads();
        if (s + NBUF < NSTAGE) issue(s + NBUF, bi);
    };

    issue(0, 0);
    issue(1, 1);
    issue(2, 2);

    #pragma unroll 1
    for (int t = 0; t < 10; t++) {
        const u32 ph = (u32)(t & 1);
        body(3 * t + 0, 0, ph);
        body(3 * t + 1, 1, ph);
        body(3 * t + 2, 2, ph);
    }
    body(30, 0, 0);
    body(31, 1, 0);

    // ---- epilogue: chan = dy*9 + dx (dx fastest) ----
    const float inv_c = 1.0f / (float)CH;
    const int gy = y0 + ty;
    const int gx = x0 + 8 * xg;
    char* outB = (char*)out;
    u32 obase = (u32)((((b * 81 + d * ND) * HH + gy) * WW + gx) * 4);
    #pragma unroll
    for (int j = 0; j < ND; j++) {
        float* o = (float*)(outB + obase);
        obase += (u32)(HH * WW * 4);
        const F2 r0 = unp(acc[j]);
        const F2 r1 = unp(acc[9 + j]);
        const F2 r2 = unp(acc[18 + j]);
        const F2 r3 = unp(acc[27 + j]);
        float4 v0 = make_float4(r0.lo * inv_c, r0.hi * inv_c, r1.lo * inv_c, r1.hi * inv_c);
        float4 v1 = make_float4(r2.lo * inv_c, r2.hi * inv_c, r3.lo * inv_c, r3.hi * inv_c);
        *reinterpret_cast<float4*>(o)     = v0;
        *reinterpret_cast<float4*>(o + 4) = v1;
    }
}

// ---------------- host side ----------------

typedef CUresult (*EncodeTiledFn)(
    CUtensorMap*, CUtensorMapDataType, cuuint32_t, void*,
    const cuuint64_t*, const cuuint64_t*, const cuuint32_t*, const cuuint32_t*,
    CUtensorMapInterleave, CUtensorMapSwizzle, CUtensorMapL2promotion,
    CUtensorMapFloatOOBfill);

static void encode_map(EncodeTiledFn enc, CUtensorMap* tm, const void* base,
                       uint32_t bx, uint32_t by) {
    cuuint64_t dims[3]    = { WW, HH, (cuuint64_t)NB * CH };
    cuuint64_t strides[2] = { WW * 4ull, (cuuint64_t)WW * HH * 4ull };
    cuuint32_t box[3]     = { bx, by, CCH };
    cuuint32_t estr[3]    = { 1, 1, 1 };
    enc(tm, CU_TENSOR_MAP_DATA_TYPE_FLOAT32, 3, const_cast<void*>(base),
        dims, strides, box, estr,
        CU_TENSOR_MAP_INTERLEAVE_NONE, CU_TENSOR_MAP_SWIZZLE_NONE,
        CU_TENSOR_MAP_L2_PROMOTION_L2_128B, CU_TENSOR_MAP_FLOAT_OOB_FILL_NONE);
}

extern "C" void kernel_launch(void* const* d_in, const int* in_sizes, int n_in,
                              void* d_out, int out_size) {
    const float* first  = (const float*)d_in[0];
    const float* second = (const float*)d_in[1];
    float* out = (float*)d_out;
    (void)in_sizes; (void)n_in; (void)out_size;

    void* fp = nullptr;
    cudaDriverEntryPointQueryResult qr;
    cudaGetDriverEntryPointByVersion("cuTensorMapEncodeTiled", &fp, 12000,
                                     cudaEnableDefault, &qr);
    EncodeTiledFn enc = (EncodeTiledFn)fp;

    CUtensorMap tmF, tmS;
    encode_map(enc, &tmF, first,  TX, TY);                       // box 32 x 8 x 4
    encode_map(enc, &tmS, second, TX + 2 * DISP, TY + 2 * DISP); // box 40 x 16 x 4

    dim3 grid(WW / TX, HH / TY, NB);   // (5, 12, 8)
    corr_kernel<<<grid, BDIM>>>(first, second, out, tmF, tmS);
}

// round 11
// speedup vs baseline: 1.9018x; 1.2566x over previous
#include <cuda_runtime.h>
#include <cuda.h>
#include <cstdint>

#define BDIM 288
#define DISP 4
#define ND 9
#define CH 128
#define HH 96
#define WW 160
#define NB 8
#define TY 8
#define TX 32
#define CCH 4
#define NBUF 3
#define NSTAGE (CH / CCH)        // 32
// Padded strides come straight from the TMA box (box0 = stride)
#define SRS 44                   // S row stride (floats) = box0
#define SROWS 16
#define SCS (SROWS * SRS)        // 704 floats / channel
#define FRS 36                   // F row stride (floats) = box0
#define FROWS 8
#define FCS (FROWS * FRS)        // 288 floats / channel
#define SBYTES (CCH * SCS * 4)   // 11264 (88*128 -> 128B aligned)
#define FBYTES (CCH * FCS * 4)   // 4608  (36*128 -> 128B aligned)
#define STAGE_BYTES (SBYTES + FBYTES)  // 15872 actual TMA bytes

typedef unsigned long long u64;
typedef unsigned int u32;

struct F2 { float lo, hi; };

static __device__ __forceinline__ u64 pk(float lo, float hi) {
    u64 r; asm("mov.b64 %0, {%1, %2};" : "=l"(r) : "f"(lo), "f"(hi)); return r;
}
static __device__ __forceinline__ F2 unp(u64 v) {
    F2 r; asm("mov.b64 {%0, %1}, %2;" : "=f"(r.lo), "=f"(r.hi) : "l"(v)); return r;
}
static __device__ __forceinline__ void fma2(u64 &d, u64 a, u64 b) {
    asm("fma.rn.f32x2 %0, %1, %2, %0;" : "+l"(d) : "l"(a), "l"(b));
}

#define MBAR_INIT(addr, cnt) \
    asm volatile("mbarrier.init.shared.b64 [%0], %1;" :: "r"(addr), "r"(cnt) : "memory")
#define MBAR_EXPECT_TX(addr, bytes) \
    asm volatile("mbarrier.arrive.expect_tx.shared.b64 _, [%0], %1;" :: "r"(addr), "r"(bytes) : "memory")
#define TMA_LD3D(smem, tmap, cx, cy, cz, mbar) \
    asm volatile("cp.async.bulk.tensor.3d.shared::cta.global.tile.mbarrier::complete_tx::bytes " \
                 "[%0], [%1, {%2, %3, %4}], [%5];" \
                 :: "r"(smem), "l"(tmap), "r"(cx), "r"(cy), "r"(cz), "r"(mbar) : "memory")

static __device__ __forceinline__ void mbar_wait(u32 addr, u32 phase) {
    asm volatile(
        "{\n\t"
        ".reg .pred P1;\n\t"
        "WAIT_LOOP_%=:\n\t"
        "mbarrier.try_wait.parity.acquire.cta.shared::cta.b64 P1, [%0], %1, 0x989680;\n\t"
        "@P1 bra.uni WAIT_DONE_%=;\n\t"
        "bra.uni WAIT_LOOP_%=;\n\t"
        "WAIT_DONE_%=:\n\t"
        "}"
        :: "r"(addr), "r"(phase) : "memory");
}

__global__ __launch_bounds__(BDIM, 2)
void corr_kernel(const float* __restrict__ first,
                 const float* __restrict__ second,
                 float* __restrict__ out,
                 const __grid_constant__ CUtensorMap tmF,
                 const __grid_constant__ CUtensorMap tmS) {
    __shared__ __align__(1024) float sS[NBUF][CCH * SCS];  // 33792 B
    __shared__ __align__(1024) float sF[NBUF][CCH * FCS];  // 13824 B
    __shared__ __align__(8) u64 mbars[NBUF];

    const int tid = threadIdx.x;
    const int b   = blockIdx.z;
    const int y0  = blockIdx.y * TY;
    const int x0  = blockIdx.x * TX;

    const int d    = tid >> 5;      // dy 0..8
    const int lane = tid & 31;
    const int ty   = lane >> 2;     // 0..7
    const int xg   = lane & 3;      // 0..3

    const u32 mb0 = (u32)__cvta_generic_to_shared(&mbars[0]);
    const u32 sS0 = (u32)__cvta_generic_to_shared(&sS[0][0]);
    const u32 sF0 = (u32)__cvta_generic_to_shared(&sF[0][0]);

    if (tid == 0) {
        MBAR_INIT(mb0 + 0,  1);
        MBAR_INIT(mb0 + 8,  1);
        MBAR_INIT(mb0 + 16, 1);
    }
    __syncthreads();

    const int zbase = b * CH;

    auto issue = [&](int s, int bi) {
        if (tid == 0) {
            const u32 mb = mb0 + bi * 8;
            MBAR_EXPECT_TX(mb, STAGE_BYTES);
            const int z = zbase + s * CCH;
            TMA_LD3D(sS0 + bi * SBYTES, &tmS, x0 - DISP, y0 - DISP, z, mb);
            TMA_LD3D(sF0 + bi * FBYTES, &tmF, x0,        y0,        z, mb);
        }
    };

    u64 acc[36];
    #pragma unroll
    for (int i = 0; i < 36; i++) acc[i] = 0ull;

    auto compute = [&](int bi) {   // bi compile-time
        const float* fptr = &sF[bi][ty * FRS + 8 * xg];
        const float* sptr = &sS[bi][(ty + d) * SRS + 8 * xg];
        #pragma unroll
        for (int cc = 0; cc < CCH; cc++) {
            const ulonglong2 F01 = *reinterpret_cast<const ulonglong2*>(fptr + cc * FCS);
            const ulonglong2 F23 = *reinterpret_cast<const ulonglong2*>(fptr + cc * FCS + 4);
            const ulonglong2 E01 = *reinterpret_cast<const ulonglong2*>(sptr + cc * SCS);
            const ulonglong2 E23 = *reinterpret_cast<const ulonglong2*>(sptr + cc * SCS + 4);
            const ulonglong2 E45 = *reinterpret_cast<const ulonglong2*>(sptr + cc * SCS + 8);
            const ulonglong2 E67 = *reinterpret_cast<const ulonglong2*>(sptr + cc * SCS + 12);

            const F2 a0 = unp(E01.x), a1 = unp(E01.y);
            const F2 a2 = unp(E23.x), a3 = unp(E23.y);
            const F2 a4 = unp(E45.x), a5 = unp(E45.y);
            const F2 a6 = unp(E67.x), a7 = unp(E67.y);

            u64 P[15];
            P[0]  = E01.x;            P[2]  = E01.y;
            P[4]  = E23.x;            P[6]  = E23.y;
            P[8]  = E45.x;            P[10] = E45.y;
            P[12] = E67.x;            P[14] = E67.y;
            P[1]  = pk(a0.hi, a1.lo); P[3]  = pk(a1.hi, a2.lo);
            P[5]  = pk(a2.hi, a3.lo); P[7]  = pk(a3.hi, a4.lo);
            P[9]  = pk(a4.hi, a5.lo); P[11] = pk(a5.hi, a6.lo);
            P[13] = pk(a6.hi, a7.lo);

            #pragma unroll
            for (int j = 0; j < ND; j++) {
                fma2(acc[j],      F01.x, P[j]);
                fma2(acc[9 + j],  F01.y, P[2 + j]);
                fma2(acc[18 + j], F23.x, P[4 + j]);
                fma2(acc[27 + j], F23.y, P[6 + j]);
            }
        }
    };

    auto body = [&](int s, int bi, u32 ph) {
        mbar_wait(mb0 + bi * 8, ph);
        compute(bi);
        __syncthreads();
        if (s + NBUF < NSTAGE) issue(s + NBUF, bi);
    };

    issue(0, 0);
    issue(1, 1);
    issue(2, 2);

    #pragma unroll 1
    for (int t = 0; t < 10; t++) {
        const u32 ph = (u32)(t & 1);
        body(3 * t + 0, 0, ph);
        body(3 * t + 1, 1, ph);
        body(3 * t + 2, 2, ph);
    }
    body(30, 0, 0);
    body(31, 1, 0);

    // ---- epilogue: chan = dy*9 + dx (dx fastest) ----
    const float inv_c = 1.0f / (float)CH;
    const int gy = y0 + ty;
    const int gx = x0 + 8 * xg;
    char* outB = (char*)out;
    u32 obase = (u32)((((b * 81 + d * ND) * HH + gy) * WW + gx) * 4);
    #pragma unroll
    for (int j = 0; j < ND; j++) {
        float* o = (float*)(outB + obase);
        obase += (u32)(HH * WW * 4);
        const F2 r0 = unp(acc[j]);
        const F2 r1 = unp(acc[9 + j]);
        const F2 r2 = unp(acc[18 + j]);
        const F2 r3 = unp(acc[27 + j]);
        float4 v0 = make_float4(r0.lo * inv_c, r0.hi * inv_c, r1.lo * inv_c, r1.hi * inv_c);
        float4 v1 = make_float4(r2.lo * inv_c, r2.hi * inv_c, r3.lo * inv_c, r3.hi * inv_c);
        *reinterpret_cast<float4*>(o)     = v0;
        *reinterpret_cast<float4*>(o + 4) = v1;
    }
}

// ---------------- host side ----------------

typedef CUresult (*EncodeTiledFn)(
    CUtensorMap*, CUtensorMapDataType, cuuint32_t, void*,
    const cuuint64_t*, const cuuint64_t*, const cuuint32_t*, const cuuint32_t*,
    CUtensorMapInterleave, CUtensorMapSwizzle, CUtensorMapL2promotion,
    CUtensorMapFloatOOBfill);

static void encode_map(EncodeTiledFn enc, CUtensorMap* tm, const void* base,
                       uint32_t bx, uint32_t by) {
    cuuint64_t dims[3]    = { WW, HH, (cuuint64_t)NB * CH };
    cuuint64_t strides[2] = { WW * 4ull, (cuuint64_t)WW * HH * 4ull };
    cuuint32_t box[3]     = { bx, by, CCH };
    cuuint32_t estr[3]    = { 1, 1, 1 };
    enc(tm, CU_TENSOR_MAP_DATA_TYPE_FLOAT32, 3, const_cast<void*>(base),
        dims, strides, box, estr,
        CU_TENSOR_MAP_INTERLEAVE_NONE, CU_TENSOR_MAP_SWIZZLE_NONE,
        CU_TENSOR_MAP_L2_PROMOTION_L2_128B, CU_TENSOR_MAP_FLOAT_OOB_FILL_NONE);
}

extern "C" void kernel_launch(void* const* d_in, const int* in_sizes, int n_in,
                              void* d_out, int out_size) {
    const float* first  = (const float*)d_in[0];
    const float* second = (const float*)d_in[1];
    float* out = (float*)d_out;
    (void)in_sizes; (void)n_in; (void)out_size;

    void* fp = nullptr;
    cudaDriverEntryPointQueryResult qr;
    cudaGetDriverEntryPointByVersion("cuTensorMapEncodeTiled", &fp, 12000,
                                     cudaEnableDefault, &qr);
    EncodeTiledFn enc = (EncodeTiledFn)fp;

    CUtensorMap tmF, tmS;
    encode_map(enc, &tmF, first,  FRS, FROWS);   // box 36 x 8  x 4 -> stride 36
    encode_map(enc, &tmS, second, SRS, SROWS);   // box 44 x 16 x 4 -> stride 44

    dim3 grid(WW / TX, HH / TY, NB);   // (5, 12, 8)
    corr_kernel<<<grid, BDIM>>>(first, second, out, tmF, tmS);
}

// round 12
// speedup vs baseline: 2.2346x; 1.1750x over previous
#include <cuda_runtime.h>
#include <cuda.h>
#include <cstdint>

#define BDIM 288
#define DISP 4
#define ND 9
#define CH 128
#define HH 96
#define WW 160
#define NB 8
#define TY 8
#define TX 32
#define CCH 8
#define NBUF 2
#define NSTAGE (CH / CCH)        // 16
// Padded strides via TMA box (box0 = smem row pitch)
#define SRS 44
#define SROWS 16
#define SCS (SROWS * SRS)        // 704 floats / channel
#define FRS 36
#define FROWS 8
#define FCS (FROWS * FRS)        // 288 floats / channel
#define SBUF_FL (CCH * SCS)      // 5632 floats per S buffer
#define FBUF_FL (CCH * FCS)      // 2304 floats per F buffer
#define SBYTES (SBUF_FL * 4)     // 22528 (128B aligned)
#define FBYTES (FBUF_FL * 4)     // 9216  (128B aligned)
#define STAGE_BYTES (SBYTES + FBYTES)    // 31744
#define SMEM_S_OFF 0
#define SMEM_F_OFF (NBUF * SBYTES)               // 45056
#define SMEM_MBAR_OFF (SMEM_F_OFF + NBUF * FBYTES) // 63488
#define SMEM_TOTAL (SMEM_MBAR_OFF + NBUF * 8)      // 63504

typedef unsigned long long u64;
typedef unsigned int u32;

struct F2 { float lo, hi; };

static __device__ __forceinline__ u64 pk(float lo, float hi) {
    u64 r; asm("mov.b64 %0, {%1, %2};" : "=l"(r) : "f"(lo), "f"(hi)); return r;
}
static __device__ __forceinline__ F2 unp(u64 v) {
    F2 r; asm("mov.b64 {%0, %1}, %2;" : "=f"(r.lo), "=f"(r.hi) : "l"(v)); return r;
}
static __device__ __forceinline__ void fma2(u64 &d, u64 a, u64 b) {
    asm("fma.rn.f32x2 %0, %1, %2, %0;" : "+l"(d) : "l"(a), "l"(b));
}

#define MBAR_INIT(addr, cnt) \
    asm volatile("mbarrier.init.shared.b64 [%0], %1;" :: "r"(addr), "r"(cnt) : "memory")
#define MBAR_EXPECT_TX(addr, bytes) \
    asm volatile("mbarrier.arrive.expect_tx.shared.b64 _, [%0], %1;" :: "r"(addr), "r"(bytes) : "memory")
#define TMA_LD3D(smem, tmap, cx, cy, cz, mbar) \
    asm volatile("cp.async.bulk.tensor.3d.shared::cta.global.tile.mbarrier::complete_tx::bytes " \
                 "[%0], [%1, {%2, %3, %4}], [%5];" \
                 :: "r"(smem), "l"(tmap), "r"(cx), "r"(cy), "r"(cz), "r"(mbar) : "memory")

static __device__ __forceinline__ void mbar_wait(u32 addr, u32 phase) {
    asm volatile(
        "{\n\t"
        ".reg .pred P1;\n\t"
        "WAIT_LOOP_%=:\n\t"
        "mbarrier.try_wait.parity.acquire.cta.shared::cta.b64 P1, [%0], %1, 0x989680;\n\t"
        "@P1 bra.uni WAIT_DONE_%=;\n\t"
        "bra.uni WAIT_LOOP_%=;\n\t"
        "WAIT_DONE_%=:\n\t"
        "}"
        :: "r"(addr), "r"(phase) : "memory");
}

__global__ __launch_bounds__(BDIM, 2)
void corr_kernel(const float* __restrict__ first,
                 const float* __restrict__ second,
                 float* __restrict__ out,
                 const __grid_constant__ CUtensorMap tmF,
                 const __grid_constant__ CUtensorMap tmS) {
    extern __shared__ __align__(1024) char smem[];
    float* sSbuf = (float*)(smem + SMEM_S_OFF);
    float* sFbuf = (float*)(smem + SMEM_F_OFF);

    const int tid = threadIdx.x;
    const int b   = blockIdx.z;
    const int y0  = blockIdx.y * TY;
    const int x0  = blockIdx.x * TX;

    const int d    = tid >> 5;      // dy 0..8
    const int lane = tid & 31;
    const int ty   = lane >> 2;     // 0..7
    const int xg   = lane & 3;      // 0..3

    const u32 base = (u32)__cvta_generic_to_shared(smem);
    const u32 sS0 = base + SMEM_S_OFF;
    const u32 sF0 = base + SMEM_F_OFF;
    const u32 mb0 = base + SMEM_MBAR_OFF;

    if (tid == 0) {
        MBAR_INIT(mb0 + 0, 1);
        MBAR_INIT(mb0 + 8, 1);
    }
    __syncthreads();

    const int zbase = b * CH;

    auto issue = [&](int s, int bi) {
        if (tid == 0) {
            const u32 mb = mb0 + bi * 8;
            MBAR_EXPECT_TX(mb, STAGE_BYTES);
            const int z = zbase + s * CCH;
            TMA_LD3D(sS0 + bi * SBYTES, &tmS, x0 - DISP, y0 - DISP, z, mb);
            TMA_LD3D(sF0 + bi * FBYTES, &tmF, x0,        y0,        z, mb);
        }
    };

    u64 acc[36];
    #pragma unroll
    for (int i = 0; i < 36; i++) acc[i] = 0ull;

    auto compute = [&](int bi) {   // bi compile-time
        const float* fptr = &sFbuf[bi * FBUF_FL + ty * FRS + 8 * xg];
        const float* sptr = &sSbuf[bi * SBUF_FL + (ty + d) * SRS + 8 * xg];
        #pragma unroll
        for (int cc = 0; cc < CCH; cc++) {
            const ulonglong2 F01 = *reinterpret_cast<const ulonglong2*>(fptr + cc * FCS);
            const ulonglong2 F23 = *reinterpret_cast<const ulonglong2*>(fptr + cc * FCS + 4);
            const ulonglong2 E01 = *reinterpret_cast<const ulonglong2*>(sptr + cc * SCS);
            const ulonglong2 E23 = *reinterpret_cast<const ulonglong2*>(sptr + cc * SCS + 4);
            const ulonglong2 E45 = *reinterpret_cast<const ulonglong2*>(sptr + cc * SCS + 8);
            const ulonglong2 E67 = *reinterpret_cast<const ulonglong2*>(sptr + cc * SCS + 12);

            const F2 a0 = unp(E01.x), a1 = unp(E01.y);
            const F2 a2 = unp(E23.x), a3 = unp(E23.y);
            const F2 a4 = unp(E45.x), a5 = unp(E45.y);
            const F2 a6 = unp(E67.x), a7 = unp(E67.y);

            u64 P[15];
            P[0]  = E01.x;            P[2]  = E01.y;
            P[4]  = E23.x;            P[6]  = E23.y;
            P[8]  = E45.x;            P[10] = E45.y;
            P[12] = E67.x;            P[14] = E67.y;
            P[1]  = pk(a0.hi, a1.lo); P[3]  = pk(a1.hi, a2.lo);
            P[5]  = pk(a2.hi, a3.lo); P[7]  = pk(a3.hi, a4.lo);
            P[9]  = pk(a4.hi, a5.lo); P[11] = pk(a5.hi, a6.lo);
            P[13] = pk(a6.hi, a7.lo);

            #pragma unroll
            for (int j = 0; j < ND; j++) {
                fma2(acc[j],      F01.x, P[j]);
                fma2(acc[9 + j],  F01.y, P[2 + j]);
                fma2(acc[18 + j], F23.x, P[4 + j]);
                fma2(acc[27 + j], F23.y, P[6 + j]);
            }
        }
    };

    auto body = [&](int s, int bi, u32 ph) {
        mbar_wait(mb0 + bi * 8, ph);
        compute(bi);
        __syncthreads();
        if (s + NBUF < NSTAGE) issue(s + NBUF, bi);
    };

    issue(0, 0);
    issue(1, 1);

    #pragma unroll 1
    for (int t = 0; t < 8; t++) {
        const u32 ph = (u32)(t & 1);
        body(2 * t + 0, 0, ph);
        body(2 * t + 1, 1, ph);
    }

    // ---- epilogue: chan = dy*9 + dx (dx fastest) ----
    const float inv_c = 1.0f / (float)CH;
    const int gy = y0 + ty;
    const int gx = x0 + 8 * xg;
    char* outB = (char*)out;
    u32 obase = (u32)((((b * 81 + d * ND) * HH + gy) * WW + gx) * 4);
    #pragma unroll
    for (int j = 0; j < ND; j++) {
        float* o = (float*)(outB + obase);
        obase += (u32)(HH * WW * 4);
        const F2 r0 = unp(acc[j]);
        const F2 r1 = unp(acc[9 + j]);
        const F2 r2 = unp(acc[18 + j]);
        const F2 r3 = unp(acc[27 + j]);
        float4 v0 = make_float4(r0.lo * inv_c, r0.hi * inv_c, r1.lo * inv_c, r1.hi * inv_c);
        float4 v1 = make_float4(r2.lo * inv_c, r2.hi * inv_c, r3.lo * inv_c, r3.hi * inv_c);
        *reinterpret_cast<float4*>(o)     = v0;
        *reinterpret_cast<float4*>(o + 4) = v1;
    }
}

// ---------------- host side ----------------

typedef CUresult (*EncodeTiledFn)(
    CUtensorMap*, CUtensorMapDataType, cuuint32_t, void*,
    const cuuint64_t*, const cuuint64_t*, const cuuint32_t*, const cuuint32_t*,
    CUtensorMapInterleave, CUtensorMapSwizzle, CUtensorMapL2promotion,
    CUtensorMapFloatOOBfill);

static void encode_map(EncodeTiledFn enc, CUtensorMap* tm, const void* base,
                       uint32_t bx, uint32_t by) {
    cuuint64_t dims[3]    = { WW, HH, (cuuint64_t)NB * CH };
    cuuint64_t strides[2] = { WW * 4ull, (cuuint64_t)WW * HH * 4ull };
    cuuint32_t box[3]     = { bx, by, CCH };
    cuuint32_t estr[3]    = { 1, 1, 1 };
    enc(tm, CU_TENSOR_MAP_DATA_TYPE_FLOAT32, 3, const_cast<void*>(base),
        dims, strides, box, estr,
        CU_TENSOR_MAP_INTERLEAVE_NONE, CU_TENSOR_MAP_SWIZZLE_NONE,
        CU_TENSOR_MAP_L2_PROMOTION_L2_128B, CU_TENSOR_MAP_FLOAT_OOB_FILL_NONE);
}

extern "C" void kernel_launch(void* const* d_in, const int* in_sizes, int n_in,
                              void* d_out, int out_size) {
    const float* first  = (const float*)d_in[0];
    const float* second = (const float*)d_in[1];
    float* out = (float*)d_out;
    (void)in_sizes; (void)n_in; (void)out_size;

    void* fp = nullptr;
    cudaDriverEntryPointQueryResult qr;
    cudaGetDriverEntryPointByVersion("cuTensorMapEncodeTiled", &fp, 12000,
                                     cudaEnableDefault, &qr);
    EncodeTiledFn enc = (EncodeTiledFn)fp;

    CUtensorMap tmF, tmS;
    encode_map(enc, &tmF, first,  FRS, FROWS);   // box 36 x 8  x 8 -> pitch 36
    encode_map(enc, &tmS, second, SRS, SROWS);   // box 44 x 16 x 8 -> pitch 44

    cudaFuncSetAttribute(corr_kernel,
                         cudaFuncAttributeMaxDynamicSharedMemorySize, SMEM_TOTAL);

    dim3 grid(WW / TX, HH / TY, NB);   // (5, 12, 8)
    corr_kernel<<<grid, BDIM, SMEM_TOTAL>>>(first, second, out, tmF, tmS);
}